// round 3
// baseline (speedup 1.0000x reference)
#include <cuda_runtime.h>
#include <cuda_bf16.h>
#include <cstdint>
#include <cstddef>

typedef __nv_bfloat16 bf16;

#define BATCH 1024
#define SEQ   80
#define EMB   100
#define UNITS 512
#define N3    1536      // 3*UNITS
#define VOCAB 10000
#define ME    10112     // vocab rows padded to 79*128
#define KE    384       // emb split-K padded (3 segs of 100 at 0/128/256)
#define KH    1536      // split-K for K=512 matrices (3*512)
#define MY    (SEQ*BATCH)

// ---------------- scratch (device globals; no allocation allowed) ----------------
__device__ bf16  g_Ae [ME*KE];            // split emb (A for E' gemm)
__device__ bf16  g_Be [N3*KE];            // split Wx1^T
__device__ bf16  g_Bh1[N3*KH];            // split Wh1^T
__device__ bf16  g_Bh2[N3*KH];            // split Wh2^T
__device__ bf16  g_Bx2[N3*KH];            // split Wx2^T
__device__ float g_Ep [(size_t)ME*N3];    // E' = emb @ Wx1
__device__ bf16  g_A1 [BATCH*KH];         // split h1 (A for L1 step gemm)
__device__ bf16  g_A2 [BATCH*KH];         // split h2 (A for L2 step gemm)
__device__ bf16  g_Y1 [(size_t)MY*KH];    // split ys1 (A for big gx2 gemm)
__device__ float g_Gx2[(size_t)MY*N3];    // ys1 @ Wx2 for all t
__device__ float g_Gh [BATCH*N3];         // step gemm output
__device__ float g_H1 [BATCH*UNITS];
__device__ float g_H2 [BATCH*UNITS];

__device__ __forceinline__ void split2(float x, bf16 &hi, bf16 &lo){
    hi = __float2bfloat16(x);
    lo = __float2bfloat16(x - __bfloat162float(hi));
}

// ---------------- asm wrappers ----------------
__device__ __forceinline__ void cp16(uint32_t dst, const void* src){
    asm volatile("cp.async.cg.shared.global [%0], [%1], 16;" :: "r"(dst), "l"(src));
}
__device__ __forceinline__ void cp_commit(){ asm volatile("cp.async.commit_group;"); }
__device__ __forceinline__ void cp_wait1(){ asm volatile("cp.async.wait_group 1;"); }
__device__ __forceinline__ void cp_wait0(){ asm volatile("cp.async.wait_group 0;"); }

__device__ __forceinline__ void ldsm4(uint32_t* d, uint32_t saddr){
    asm volatile("ldmatrix.sync.aligned.m8n8.x4.shared.b16 {%0,%1,%2,%3}, [%4];"
        : "=r"(d[0]), "=r"(d[1]), "=r"(d[2]), "=r"(d[3]) : "r"(saddr));
}
__device__ __forceinline__ void mma16816(float* c, const uint32_t* a, uint32_t bb0, uint32_t bb1){
    asm volatile("mma.sync.aligned.m16n8k16.row.col.f32.bf16.bf16.f32 "
        "{%0,%1,%2,%3}, {%4,%5,%6,%7}, {%8,%9}, {%0,%1,%2,%3};"
        : "+f"(c[0]), "+f"(c[1]), "+f"(c[2]), "+f"(c[3])
        : "r"(a[0]), "r"(a[1]), "r"(a[2]), "r"(a[3]), "r"(bb0), "r"(bb1));
}

// ---------------- weight / embedding split kernels ----------------
// A layout along K': [hi | hi | lo], B layout: [hi | lo | hi]
// => products hi*hi + hi*lo + lo*hi  (residual lo*lo ~ 2^-16)

__global__ void k_split_emb(const float* __restrict__ emb){
    int idx = blockIdx.x*blockDim.x + threadIdx.x;
    if (idx >= ME*KE) return;
    int row = idx / KE, k = idx % KE;
    int sel = -1; int kk = 0;
    if (row < VOCAB){
        if (k < EMB)                      { sel = 0; kk = k;       }
        else if (k >= 128 && k < 128+EMB) { sel = 0; kk = k - 128; }
        else if (k >= 256 && k < 256+EMB) { sel = 1; kk = k - 256; }
    }
    bf16 out = __float2bfloat16(0.f);
    if (sel >= 0){
        bf16 hi, lo; split2(emb[row*EMB + kk], hi, lo);
        out = (sel == 0) ? hi : lo;
    }
    g_Ae[idx] = out;
}

__global__ void k_split_Be(const float* __restrict__ Wx1){
    int idx = blockIdx.x*blockDim.x + threadIdx.x;
    if (idx >= N3*KE) return;
    int n = idx / KE, k = idx % KE;
    int sel = -1, kk = 0;
    if (k < EMB)                      { sel = 0; kk = k;       }   // hi
    else if (k >= 128 && k < 128+EMB) { sel = 1; kk = k - 128; }   // lo
    else if (k >= 256 && k < 256+EMB) { sel = 0; kk = k - 256; }   // hi
    bf16 out = __float2bfloat16(0.f);
    if (sel >= 0){
        bf16 hi, lo; split2(Wx1[kk*N3 + n], hi, lo);
        out = (sel == 0) ? hi : lo;
    }
    g_Be[idx] = out;
}

__global__ void k_split_B512(const float* __restrict__ W, bf16* __restrict__ out){
    int idx = blockIdx.x*blockDim.x + threadIdx.x;
    if (idx >= N3*KH) return;
    int n = idx / KH, k = idx % KH;
    int sel, kk;
    if (k < 512)       { sel = 0; kk = k;        }   // hi
    else if (k < 1024) { sel = 1; kk = k - 512;  }   // lo
    else               { sel = 0; kk = k - 1024; }   // hi
    bf16 hi, lo; split2(W[kk*N3 + n], hi, lo);
    out[idx] = (sel == 0) ? hi : lo;
}

// ---------------- GEMM: C[M,1536] = A[M,K] * B^T[1536,K], bf16 in / fp32 out ----------------
// BM=128 BN=128 BK=32, 256 threads (8 warps: 4 in M x 2 in N), mma m16n8k16.

__device__ __forceinline__ int swzoff(int r, int c){
    // half-element offset into a 128x32 bf16 tile; c = 16B chunk (0..3)
    return r*32 + (((c ^ (r & 3) ^ ((r >> 2) & 3)) & 3) << 3);
}

__global__ void __launch_bounds__(256) k_gemm(
    const bf16* __restrict__ A, const bf16* __restrict__ Bt,
    float* __restrict__ C, int K)
{
    __shared__ __align__(16) bf16 As[2][128*32];
    __shared__ __align__(16) bf16 Bs[2][128*32];

    const int tid  = threadIdx.x;
    const int lane = tid & 31;
    const int warp = tid >> 5;
    const int wm   = warp & 3;   // M sub-tile (32 rows each)
    const int wn   = warp >> 2;  // N sub-tile (64 cols each)
    const long m0  = (long)blockIdx.y * 128;
    const long n0  = (long)blockIdx.x * 128;
    const bf16* Ag = A  + m0 * K;
    const bf16* Bg = Bt + n0 * K;

    uint32_t sA[2], sB[2];
    sA[0] = (uint32_t)__cvta_generic_to_shared(&As[0][0]);
    sA[1] = (uint32_t)__cvta_generic_to_shared(&As[1][0]);
    sB[0] = (uint32_t)__cvta_generic_to_shared(&Bs[0][0]);
    sB[1] = (uint32_t)__cvta_generic_to_shared(&Bs[1][0]);

    float acc[2][8][4];
    #pragma unroll
    for (int i=0;i<2;i++)
        #pragma unroll
        for (int j=0;j<8;j++)
            #pragma unroll
            for (int q=0;q<4;q++) acc[i][j][q] = 0.f;

    const int nk = K >> 5;

    // prologue: load tile 0
    {
        #pragma unroll
        for (int i=0;i<2;i++){
            int q = tid + (i<<8);
            int r = q >> 2, c = q & 3;
            cp16(sA[0] + swzoff(r,c)*2, Ag + (long)r*K + c*8);
            cp16(sB[0] + swzoff(r,c)*2, Bg + (long)r*K + c*8);
        }
        cp_commit();
    }

    for (int kt = 0; kt < nk; kt++){
        const int s = kt & 1;
        if (kt + 1 < nk){
            #pragma unroll
            for (int i=0;i<2;i++){
                int q = tid + (i<<8);
                int r = q >> 2, c = q & 3;
                long koff = (long)(kt+1)*32 + c*8;
                cp16(sA[s^1] + swzoff(r,c)*2, Ag + (long)r*K + koff);
                cp16(sB[s^1] + swzoff(r,c)*2, Bg + (long)r*K + koff);
            }
            cp_commit();
            cp_wait1();
        } else {
            cp_wait0();
        }
        __syncthreads();

        #pragma unroll
        for (int kk = 0; kk < 2; kk++){     // two k16 steps per 32-K tile
            uint32_t areg[2][4];
            uint32_t breg[4][4];
            #pragma unroll
            for (int i=0;i<2;i++){
                int r = wm*32 + i*16 + (lane & 15);
                int c = (kk<<1) + (lane >> 4);
                ldsm4(areg[i], sA[s] + (uint32_t)swzoff(r,c)*2);
            }
            #pragma unroll
            for (int g=0; g<4; g++){
                int r = wn*64 + g*16 + (lane & 15);
                int c = (kk<<1) + (lane >> 4);
                ldsm4(breg[g], sB[s] + (uint32_t)swzoff(r,c)*2);
            }
            #pragma unroll
            for (int i=0;i<2;i++)
                #pragma unroll
                for (int j=0;j<8;j++){
                    int g = j >> 1, h = j & 1;
                    mma16816(acc[i][j], areg[i], breg[g][h], breg[g][h+2]);
                }
        }
        __syncthreads();
    }

    // epilogue: fp32 store
    #pragma unroll
    for (int i=0;i<2;i++){
        long row = m0 + wm*32 + i*16 + (lane >> 2);
        #pragma unroll
        for (int j=0;j<8;j++){
            long col = n0 + wn*64 + j*8 + ((lane & 3) << 1);
            *(float2*)&C[row*N3 + col]     = make_float2(acc[i][j][0], acc[i][j][1]);
            *(float2*)&C[(row+8)*N3 + col] = make_float2(acc[i][j][2], acc[i][j][3]);
        }
    }
}

// ---------------- fused gate kernels ----------------
__global__ void __launch_bounds__(256) k_gate1(const int* __restrict__ tokens,
                                               const float* __restrict__ b1,
                                               int t, bf16* __restrict__ Y1t)
{
    int idx = blockIdx.x*blockDim.x + threadIdx.x;   // BATCH*UNITS threads
    int b = idx >> 9, u = idx & 511;
    int tok = tokens[b*SEQ + t];
    const float* e  = g_Ep + (size_t)tok*N3;
    const float* gh = g_Gh + (size_t)b*N3;
    float xz = e[u]        + b1[u];
    float xr = e[u+512]    + b1[u+512];
    float xh = e[u+1024]   + b1[u+1024];
    float hz = gh[u]       + b1[N3+u];
    float hr = gh[u+512]   + b1[N3+512+u];
    float hn = gh[u+1024]  + b1[N3+1024+u];
    float z  = 1.f/(1.f + expf(-(xz+hz)));
    float r  = 1.f/(1.f + expf(-(xr+hr)));
    float hh = tanhf(xh + r*hn);
    float h  = z*g_H1[idx] + (1.f-z)*hh;
    g_H1[idx] = h;
    bf16 hi, lo; split2(h, hi, lo);
    size_t base = (size_t)b*KH;
    g_A1[base + u]        = hi;
    g_A1[base + 512 + u]  = hi;
    g_A1[base + 1024 + u] = lo;
    Y1t[base + u]         = hi;
    Y1t[base + 512 + u]   = hi;
    Y1t[base + 1024 + u]  = lo;
}

__global__ void __launch_bounds__(256) k_gate2(const float* __restrict__ b2,
                                               const float* __restrict__ gx)
{
    int idx = blockIdx.x*blockDim.x + threadIdx.x;
    int b = idx >> 9, u = idx & 511;
    const float* x  = gx   + (size_t)b*N3;
    const float* gh = g_Gh + (size_t)b*N3;
    float xz = x[u]       + b2[u];
    float xr = x[u+512]   + b2[u+512];
    float xh = x[u+1024]  + b2[u+1024];
    float hz = gh[u]      + b2[N3+u];
    float hr = gh[u+512]  + b2[N3+512+u];
    float hn = gh[u+1024] + b2[N3+1024+u];
    float z  = 1.f/(1.f + expf(-(xz+hz)));
    float r  = 1.f/(1.f + expf(-(xr+hr)));
    float hh = tanhf(xh + r*hn);
    float h  = z*g_H2[idx] + (1.f-z)*hh;
    g_H2[idx] = h;
    bf16 hi, lo; split2(h, hi, lo);
    size_t base = (size_t)b*KH;
    g_A2[base + u]        = hi;
    g_A2[base + 512 + u]  = hi;
    g_A2[base + 1024 + u] = lo;
}

// ---------------- final dense + sigmoid ----------------
__global__ void __launch_bounds__(256) k_final(const float* __restrict__ Wfc,
                                               const float* __restrict__ bfc,
                                               float* __restrict__ out)
{
    int gtid = blockIdx.x*blockDim.x + threadIdx.x;
    int w = gtid >> 5, lane = gtid & 31;
    if (w >= BATCH) return;
    float s = 0.f;
    for (int u = lane; u < UNITS; u += 32) s += g_H2[w*UNITS + u] * Wfc[u];
    #pragma unroll
    for (int o = 16; o > 0; o >>= 1) s += __shfl_xor_sync(0xffffffffu, s, o);
    if (lane == 0) out[w] = 1.f/(1.f + expf(-(s + bfc[0])));
}

// ---------------- host ----------------
extern "C" void kernel_launch(void* const* d_in, const int* in_sizes, int n_in,
                              void* d_out, int out_size)
{
    const int*   tokens = (const int*)  d_in[0];
    const float* emb    = (const float*)d_in[1];
    const float* Wx1    = (const float*)d_in[2];
    const float* Wh1    = (const float*)d_in[3];
    const float* b1     = (const float*)d_in[4];
    const float* Wx2    = (const float*)d_in[5];
    const float* Wh2    = (const float*)d_in[6];
    const float* b2     = (const float*)d_in[7];
    const float* Wfc    = (const float*)d_in[8];
    const float* bfc    = (const float*)d_in[9];

    bf16 *pAe, *pBe, *pBh1, *pBh2, *pBx2, *pA1, *pA2, *pY1;
    float *pEp, *pGx2, *pGh, *pH1, *pH2;
    cudaGetSymbolAddress((void**)&pAe,  g_Ae);
    cudaGetSymbolAddress((void**)&pBe,  g_Be);
    cudaGetSymbolAddress((void**)&pBh1, g_Bh1);
    cudaGetSymbolAddress((void**)&pBh2, g_Bh2);
    cudaGetSymbolAddress((void**)&pBx2, g_Bx2);
    cudaGetSymbolAddress((void**)&pA1,  g_A1);
    cudaGetSymbolAddress((void**)&pA2,  g_A2);
    cudaGetSymbolAddress((void**)&pY1,  g_Y1);
    cudaGetSymbolAddress((void**)&pEp,  g_Ep);
    cudaGetSymbolAddress((void**)&pGx2, g_Gx2);
    cudaGetSymbolAddress((void**)&pGh,  g_Gh);
    cudaGetSymbolAddress((void**)&pH1,  g_H1);
    cudaGetSymbolAddress((void**)&pH2,  g_H2);

    // 1. split weights / embeddings (bf16 hi/lo, K-stacked)
    k_split_emb <<<(ME*KE + 255)/256, 256>>>(emb);
    k_split_Be  <<<(N3*KE + 255)/256, 256>>>(Wx1);
    k_split_B512<<<(N3*KH + 255)/256, 256>>>(Wh1, pBh1);
    k_split_B512<<<(N3*KH + 255)/256, 256>>>(Wh2, pBh2);
    k_split_B512<<<(N3*KH + 255)/256, 256>>>(Wx2, pBx2);

    // 2. zero initial state (h0 = 0, and its splits)
    cudaMemsetAsync(pA1, 0, (size_t)BATCH*KH*sizeof(bf16));
    cudaMemsetAsync(pA2, 0, (size_t)BATCH*KH*sizeof(bf16));
    cudaMemsetAsync(pH1, 0, (size_t)BATCH*UNITS*sizeof(float));
    cudaMemsetAsync(pH2, 0, (size_t)BATCH*UNITS*sizeof(float));

    // 3. E' = emb @ Wx1  (per-vocab-word precompute)
    k_gemm<<<dim3(12, ME/128), 256>>>(pAe, pBe, pEp, KE);

    // 4. layer-1 recurrence
    for (int t = 0; t < SEQ; t++){
        k_gemm <<<dim3(12, BATCH/128), 256>>>(pA1, pBh1, pGh, KH);
        k_gate1<<<(BATCH*UNITS)/256, 256>>>(tokens, b1, t, pY1 + (size_t)t*BATCH*KH);
    }

    // 5. batched gx2 = ys1 @ Wx2 for all timesteps
    k_gemm<<<dim3(12, MY/128), 256>>>(pY1, pBx2, pGx2, KH);

    // 6. layer-2 recurrence
    for (int t = 0; t < SEQ; t++){
        k_gemm <<<dim3(12, BATCH/128), 256>>>(pA2, pBh2, pGh, KH);
        k_gate2<<<(BATCH*UNITS)/256, 256>>>(b2, pGx2 + (size_t)t*BATCH*N3);
    }

    // 7. logits + sigmoid
    k_final<<<(BATCH/8 + 0), 256>>>(Wfc, bfc, (float*)d_out);
}